// round 2
// baseline (speedup 1.0000x reference)
#include <cuda_runtime.h>
#include <math.h>

// ---------------------------------------------------------------------------
// CLIP contrastive loss, fully fused (CUDA-core fp32 baseline, v2).
//   logits = scale * img @ txt^T   (16384 x 16384, never materialized)
//   loss = 0.5*( mean_i[LSE_row(i) - diag(i)] + mean_i[LSE_col(i) - diag(i)] )
// All internal math in log2 units.
// v2: 256 CTAs (each 128-row stripe split into two 64-column-tile halves),
//     BK=32, 2 CTAs/SM for latency hiding.
// ---------------------------------------------------------------------------

#define NTOK 16384
#define DK   512
#define BM   128
#define BN   128
#define BK   32
#define NSTRIPE (NTOK / BM)   // 128
#define NCTILE  (NTOK / BN)   // 128
#define NHALF   2
#define TILES_PER_HALF (NCTILE / NHALF)  // 64

#define LOG2E_F 1.4426950408889634f
#define LN2_D   0.6931471805599453

// Scratch (device globals -- no allocations allowed).
// Every element is overwritten on every launch => graph-replay safe.
__device__ float g_colM[NSTRIPE * NTOK];      // per-(stripe,col) partial max (8 MB)
__device__ float g_colS[NSTRIPE * NTOK];      // per-(stripe,col) partial sum (8 MB)
__device__ float g_rowM[NHALF * NTOK];        // per-(half,row) partial max
__device__ float g_rowS[NHALF * NTOK];        // per-(half,row) partial sum
__device__ float g_diag[NSTRIPE * NHALF];     // per-CTA diagonal sums
__device__ float g_colPart[NCTILE];           // kernel2 partial sums of col LSEs
__device__ float g_rowPart[NSTRIPE];          // kernel2b partial sums of row LSEs

// ---------------------------------------------------------------------------
// Kernel 1: one CTA per (stripe, half). 256 threads, 8x8 register tiles.
// ---------------------------------------------------------------------------
__global__ void __launch_bounds__(256, 2)
clip_main_kernel(const float* __restrict__ A,     // image_features [NTOK][DK]
                 const float* __restrict__ B,     // text_features  [NTOK][DK]
                 const float* __restrict__ scale_p)
{
    __shared__ float As[BK * BM];                // 16 KB
    __shared__ float Bs[BK * BN];                // 16 KB
    __shared__ float red[16 * 128];              // 8 KB (reused)
    __shared__ float colmax_sm[128];

    const int b   = blockIdx.x >> 1;             // stripe (rows b*128 .. +128)
    const int h   = blockIdx.x & 1;              // column half
    const int tid = threadIdx.x;
    const int tx  = tid & 15;                    // column group (cols tx*8..+8)
    const int ty  = tid >> 4;                    // row group    (rows ty*8..+8)

    const float f = scale_p[0] * LOG2E_F;        // fold scale and log2(e)

    float rm[8], rs[8];
#pragma unroll
    for (int r = 0; r < 8; ++r) { rm[r] = -INFINITY; rs[r] = 0.0f; }
    float diagAcc = 0.0f;

    const float* Arow = A + (size_t)b * BM * DK;

    const int j0 = h * TILES_PER_HALF;
    for (int jj = 0; jj < TILES_PER_HALF; ++jj) {
        const int j = j0 + jj;
        const float* Brow = B + (size_t)j * BN * DK;

        float acc[8][8];
#pragma unroll
        for (int r = 0; r < 8; ++r)
#pragma unroll
            for (int c = 0; c < 8; ++c) acc[r][c] = 0.0f;

        for (int kc = 0; kc < DK / BK; ++kc) {
            // load 128x32 chunks of A and B, transposed into SMEM [k][m]
#pragma unroll
            for (int i = 0; i < 4; ++i) {
                int idx = tid + i * 256;         // 0..1023 float4 loads / matrix
                int m   = idx >> 3;              // 0..127
                int kv  = idx & 7;               // 0..7 (4 floats each)
                float4 va = *(const float4*)(Arow + (size_t)m * DK + kc * BK + kv * 4);
                float4 vb = *(const float4*)(Brow + (size_t)m * DK + kc * BK + kv * 4);
                As[(kv * 4 + 0) * BM + m] = va.x;
                As[(kv * 4 + 1) * BM + m] = va.y;
                As[(kv * 4 + 2) * BM + m] = va.z;
                As[(kv * 4 + 3) * BM + m] = va.w;
                Bs[(kv * 4 + 0) * BN + m] = vb.x;
                Bs[(kv * 4 + 1) * BN + m] = vb.y;
                Bs[(kv * 4 + 2) * BN + m] = vb.z;
                Bs[(kv * 4 + 3) * BN + m] = vb.w;
            }
            __syncthreads();

#pragma unroll
            for (int k = 0; k < BK; ++k) {
                float4 a0 = *(const float4*)&As[k * BM + ty * 8];
                float4 a1 = *(const float4*)&As[k * BM + ty * 8 + 4];
                float4 b0 = *(const float4*)&Bs[k * BN + tx * 8];
                float4 b1 = *(const float4*)&Bs[k * BN + tx * 8 + 4];
                float av[8] = {a0.x, a0.y, a0.z, a0.w, a1.x, a1.y, a1.z, a1.w};
                float bv[8] = {b0.x, b0.y, b0.z, b0.w, b1.x, b1.y, b1.z, b1.w};
#pragma unroll
                for (int r = 0; r < 8; ++r)
#pragma unroll
                    for (int c = 0; c < 8; ++c)
                        acc[r][c] = fmaf(av[r], bv[c], acc[r][c]);
            }
            __syncthreads();
        }

        // scale into log2 units
#pragma unroll
        for (int r = 0; r < 8; ++r)
#pragma unroll
            for (int c = 0; c < 8; ++c) acc[r][c] *= f;

        // diagonal (only tile j == b, threads with ty == tx)
        if (j == b && ty == tx) {
#pragma unroll
            for (int r = 0; r < 8; ++r) diagAcc += acc[r][r];
        }

        // online row update (per-thread partial over its 8 columns)
#pragma unroll
        for (int r = 0; r < 8; ++r) {
            float tm = acc[r][0];
#pragma unroll
            for (int c = 1; c < 8; ++c) tm = fmaxf(tm, acc[r][c]);
            if (tm > rm[r] - 87.0f) {            // else contribution < 2^-87
                float nm = fmaxf(rm[r], tm);
                float s  = 0.0f;
#pragma unroll
                for (int c = 0; c < 8; ++c) s += exp2f(acc[r][c] - nm);
                rs[r] = rs[r] * exp2f(rm[r] - nm) + s;
                rm[r] = nm;
            }
        }

        // column partials for this tile (reduce over 128 rows)
        float cmx[8];
#pragma unroll
        for (int c = 0; c < 8; ++c) {
            float m = acc[0][c];
#pragma unroll
            for (int r = 1; r < 8; ++r) m = fmaxf(m, acc[r][c]);
            cmx[c] = m;
            red[ty * 128 + tx * 8 + c] = m;
        }
        __syncthreads();
        if (tid < 128) {
            float m = red[tid];
#pragma unroll
            for (int t = 1; t < 16; ++t) m = fmaxf(m, red[t * 128 + tid]);
            colmax_sm[tid] = m;
        }
        __syncthreads();
#pragma unroll
        for (int c = 0; c < 8; ++c) {
            float cm = colmax_sm[tx * 8 + c];
            float ps = 0.0f;
            if (cmx[c] > cm - 87.0f) {
#pragma unroll
                for (int r = 0; r < 8; ++r) ps += exp2f(acc[r][c] - cm);
            }
            red[ty * 128 + tx * 8 + c] = ps;
        }
        __syncthreads();
        if (tid < 128) {
            float s = 0.0f;
#pragma unroll
            for (int t = 0; t < 16; ++t) s += red[t * 128 + tid];
            g_colM[(size_t)b * NTOK + j * BN + tid] = colmax_sm[tid];
            g_colS[(size_t)b * NTOK + j * BN + tid] = s;
        }
        __syncthreads();   // red/colmax_sm reused next iteration
    }

    // combine row partials across the 16 tx-threads sharing each row,
    // then store this half's per-row (m, s) to global.
#pragma unroll
    for (int r = 0; r < 8; ++r) {
        float m = rm[r], s = rs[r];
#pragma unroll
        for (int off = 8; off >= 1; off >>= 1) {
            float mo = __shfl_xor_sync(0xffffffffu, m, off);
            float so = __shfl_xor_sync(0xffffffffu, s, off);
            float M  = fmaxf(m, mo);
            s = s * exp2f(m - M) + so * exp2f(mo - M);
            m = M;
        }
        if (tx == 0) {
            int row = b * BM + ty * 8 + r;
            g_rowM[h * NTOK + row] = m;
            g_rowS[h * NTOK + row] = s;
        }
    }

    // per-CTA diagonal sum
    red[tid] = diagAcc;
    __syncthreads();
    for (int off = 128; off >= 1; off >>= 1) {
        if (tid < off) red[tid] += red[tid + off];
        __syncthreads();
    }
    if (tid == 0) g_diag[blockIdx.x] = red[0];
}

// ---------------------------------------------------------------------------
// Kernel 2: column LSEs. 128 blocks x 128 threads (one thread per column).
// ---------------------------------------------------------------------------
__global__ void __launch_bounds__(128)
clip_colreduce_kernel()
{
    __shared__ float sred[128];
    const int col = blockIdx.x * 128 + threadIdx.x;

    float m = -INFINITY, S = 0.0f;
    for (int s = 0; s < NSTRIPE; ++s) {
        float mm = g_colM[(size_t)s * NTOK + col];
        float ss = g_colS[(size_t)s * NTOK + col];
        float M  = fmaxf(m, mm);
        S = S * exp2f(m - M) + ss * exp2f(mm - M);
        m = M;
    }
    sred[threadIdx.x] = m + log2f(S);
    __syncthreads();
    for (int off = 64; off >= 1; off >>= 1) {
        if (threadIdx.x < off) sred[threadIdx.x] += sred[threadIdx.x + off];
        __syncthreads();
    }
    if (threadIdx.x == 0) g_colPart[blockIdx.x] = sred[0];
}

// ---------------------------------------------------------------------------
// Kernel 2b: row LSEs (merge the two half partials). 128 blocks x 128 thr.
// ---------------------------------------------------------------------------
__global__ void __launch_bounds__(128)
clip_rowreduce_kernel()
{
    __shared__ float sred[128];
    const int row = blockIdx.x * 128 + threadIdx.x;

    float m0 = g_rowM[row],        s0 = g_rowS[row];
    float m1 = g_rowM[NTOK + row], s1 = g_rowS[NTOK + row];
    float M  = fmaxf(m0, m1);
    float S  = s0 * exp2f(m0 - M) + s1 * exp2f(m1 - M);

    sred[threadIdx.x] = M + log2f(S);
    __syncthreads();
    for (int off = 64; off >= 1; off >>= 1) {
        if (threadIdx.x < off) sred[threadIdx.x] += sred[threadIdx.x + off];
        __syncthreads();
    }
    if (threadIdx.x == 0) g_rowPart[blockIdx.x] = sred[0];
}

// ---------------------------------------------------------------------------
// Kernel 3: final scalar combine.
// ---------------------------------------------------------------------------
__global__ void clip_final_kernel(float* __restrict__ out)
{
    if (threadIdx.x == 0 && blockIdx.x == 0) {
        double rsum = 0.0, csum = 0.0, dsum = 0.0;
        for (int i = 0; i < NSTRIPE; ++i) {
            rsum += (double)g_rowPart[i];
            csum += (double)g_colPart[i];
        }
        for (int i = 0; i < NSTRIPE * NHALF; ++i) dsum += (double)g_diag[i];
        // loss = ln2 * ( 0.5*(sum_row_lse2 + sum_col_lse2) - sum_diag2 ) / N
        double loss = LN2_D * (0.5 * (rsum + csum) - dsum) / (double)NTOK;
        out[0] = (float)loss;
    }
}

// ---------------------------------------------------------------------------
extern "C" void kernel_launch(void* const* d_in, const int* in_sizes, int n_in,
                              void* d_out, int out_size)
{
    const float* img   = (const float*)d_in[0];
    const float* txt   = (const float*)d_in[1];
    const float* scale = (const float*)d_in[2];
    float* out = (float*)d_out;

    clip_main_kernel<<<NSTRIPE * NHALF, 256>>>(img, txt, scale);
    clip_colreduce_kernel<<<NCTILE, 128>>>();
    clip_rowreduce_kernel<<<NSTRIPE, 128>>>();
    clip_final_kernel<<<1, 32>>>(out);
}

// round 5
// speedup vs baseline: 5.3115x; 5.3115x over previous
#include <cuda_runtime.h>
#include <cuda_bf16.h>
#include <math.h>
#include <stdint.h>

// ===========================================================================
// CLIP contrastive loss, single-pass warp-MMA (mma.sync bf16, sm_100-safe).
//   logits = scale * img @ txt^T  computed tile-by-tile (never materialized).
//   Each CTA(i,j): 128x128 tile. Row stats per warp-half (128x64),
//   col stats per warp-quarter (32x128). All math in log2 units.
// ===========================================================================

#define NTOK 16384
#define DK   512
#define NT   128            // 128x128 tiles per dimension
#define BK   32
#define NSTG (DK / BK)      // 16

#define LOG2E_F 1.4426950408889634f
#define LN2_D   0.6931471805599453
#define SKIP_THR 25.0f

// ------------------------- device scratch ---------------------------------
__device__ __nv_bfloat16 g_bfA[NTOK * DK];      // image bf16 (16 MB)
__device__ __nv_bfloat16 g_bfB[NTOK * DK];      // text  bf16 (16 MB)
__device__ float g_rowM[256u * NTOK];           // [j*2+wc][row]  (16.8 MB)
__device__ float g_rowS[256u * NTOK];
__device__ float g_colM[512u * NTOK];           // [i*4+wr][col]  (33.6 MB)
__device__ float g_colS[512u * NTOK];
__device__ float g_diagBlk[NT];
__device__ float g_lseR[128];
__device__ float g_lseC[128];

// ------------------------- PTX helpers ------------------------------------
__device__ __forceinline__ uint32_t smem_u32(const void* p) {
    uint32_t a;
    asm("{ .reg .u64 t; cvta.to.shared.u64 t, %1; cvt.u32.u64 %0, t; }"
        : "=r"(a) : "l"(p));
    return a;
}
__device__ __forceinline__ void cpasync16(uint32_t dst, const void* src) {
    asm volatile("cp.async.cg.shared.global [%0], [%1], 16;"
                 :: "r"(dst), "l"(src) : "memory");
}
#define CP_COMMIT() asm volatile("cp.async.commit_group;" ::: "memory")

__device__ __forceinline__ void ldsm_x4(uint32_t* r, uint32_t addr) {
    asm volatile("ldmatrix.sync.aligned.m8n8.x4.shared.b16 {%0,%1,%2,%3}, [%4];"
                 : "=r"(r[0]), "=r"(r[1]), "=r"(r[2]), "=r"(r[3]) : "r"(addr));
}
__device__ __forceinline__ void mma16816(float* d, const uint32_t* a,
                                         const uint32_t* b) {
    asm volatile(
        "mma.sync.aligned.m16n8k16.row.col.f32.bf16.bf16.f32 "
        "{%0,%1,%2,%3}, {%4,%5,%6,%7}, {%8,%9}, {%0,%1,%2,%3};"
        : "+f"(d[0]), "+f"(d[1]), "+f"(d[2]), "+f"(d[3])
        : "r"(a[0]), "r"(a[1]), "r"(a[2]), "r"(a[3]), "r"(b[0]), "r"(b[1]));
}

// ---------------------------------------------------------------------------
// Kernel 0: fp32 -> bf16 conversion of both inputs.
// ---------------------------------------------------------------------------
__global__ void __launch_bounds__(256)
convert_kernel(const float* __restrict__ A, const float* __restrict__ B)
{
    const int gb = blockIdx.x;
    const bool isB = (gb >= 8192);
    const float* src = isB ? B : A;
    __nv_bfloat16* dst = isB ? g_bfB : g_bfA;
    size_t i = ((size_t)(gb & 8191) * 256 + threadIdx.x) * 4;
    float4 v = *(const float4*)(src + i);
    *(__nv_bfloat162*)(dst + i)     = __floats2bfloat162_rn(v.x, v.y);
    *(__nv_bfloat162*)(dst + i + 2) = __floats2bfloat162_rn(v.z, v.w);
}

// ---------------------------------------------------------------------------
// stage loader: A and B 128x32 bf16 chunks into padded smem (stride 40 elems).
// ---------------------------------------------------------------------------
__device__ __forceinline__ void load_stage(uint32_t dA, uint32_t dB,
                                           const __nv_bfloat16* Ab,
                                           const __nv_bfloat16* Bb,
                                           int kb, int tid)
{
#pragma unroll
    for (int t = 0; t < 2; ++t) {
        int idx = tid + t * 256;         // 0..511
        int row = idx >> 2;              // 0..127
        int ch  = idx & 3;               // 0..3, 16B each
        size_t gsrc = (size_t)row * 1024 + (size_t)kb * 64 + ch * 16;  // bytes
        uint32_t doff = row * 80 + ch * 16;                            // bytes
        cpasync16(dA + doff, (const char*)Ab + gsrc);
        cpasync16(dB + doff, (const char*)Bb + gsrc);
    }
}

// ---------------------------------------------------------------------------
// Kernel 1: fused GEMM + row/col softmax stats. grid=(128,128), 256 threads.
// ---------------------------------------------------------------------------
__global__ void __launch_bounds__(256)
clip_mma_kernel(const float* __restrict__ scale_p)
{
    __shared__ __align__(16) __nv_bfloat16 sA[2][128 * 40];   // 20 KB
    __shared__ __align__(16) __nv_bfloat16 sB[2][128 * 40];   // 20 KB
    __shared__ float sred[256];

    const int tid  = threadIdx.x;
    const int lane = tid & 31;
    const int warp = tid >> 5;
    const int wr   = warp & 3;           // row quarter: rows wr*32..+32
    const int wc   = warp >> 2;          // col half:    cols wc*64..+64
    const int j = blockIdx.x, i = blockIdx.y;

    const __nv_bfloat16* Ab = g_bfA + (size_t)i * 128 * DK;
    const __nv_bfloat16* Bb = g_bfB + (size_t)j * 128 * DK;
    const float fsc = scale_p[0] * LOG2E_F;

    float acc[2][8][4];
#pragma unroll
    for (int mt = 0; mt < 2; ++mt)
#pragma unroll
        for (int nt = 0; nt < 8; ++nt)
#pragma unroll
            for (int r = 0; r < 4; ++r) acc[mt][nt][r] = 0.0f;

    const uint32_t aS = smem_u32(sA), bS = smem_u32(sB);
    // ldmatrix per-thread address components (bytes, within a stage)
    const uint32_t aOff = ((wr * 32 + (lane & 15)) * 40 + ((lane >> 4) << 3)) * 2;
    const uint32_t bOff = ((wc * 64 + (lane & 7) + ((lane >> 4) << 3)) * 40
                          + (((lane >> 3) & 1) << 3)) * 2;

    load_stage(aS, bS, Ab, Bb, 0, tid);
    CP_COMMIT();
    load_stage(aS + 10240, bS + 10240, Ab, Bb, 1, tid);
    CP_COMMIT();

    for (int kb = 0; kb < NSTG; ++kb) {
        const int s = kb & 1;
        if (kb < NSTG - 1) asm volatile("cp.async.wait_group 1;" ::: "memory");
        else               asm volatile("cp.async.wait_group 0;" ::: "memory");
        __syncthreads();

        const uint32_t aBase = aS + s * 10240 + aOff;
        const uint32_t bBase = bS + s * 10240 + bOff;
#pragma unroll
        for (int kk = 0; kk < 2; ++kk) {
            uint32_t a[2][4], b[4][4];
            ldsm_x4(a[0], aBase + kk * 32);
            ldsm_x4(a[1], aBase + kk * 32 + 16 * 80);
#pragma unroll
            for (int p = 0; p < 4; ++p)
                ldsm_x4(b[p], bBase + kk * 32 + p * 16 * 80);
#pragma unroll
            for (int mt = 0; mt < 2; ++mt)
#pragma unroll
                for (int p = 0; p < 4; ++p) {
                    mma16816(acc[mt][2 * p],     a[mt], &b[p][0]);
                    mma16816(acc[mt][2 * p + 1], a[mt], &b[p][2]);
                }
        }
        __syncthreads();
        if (kb <= NSTG - 3) {
            load_stage(aS + s * 10240, bS + s * 10240, Ab, Bb, kb + 2, tid);
            CP_COMMIT();
        }
    }

    // ---- scale into log2 units -------------------------------------------
#pragma unroll
    for (int mt = 0; mt < 2; ++mt)
#pragma unroll
        for (int nt = 0; nt < 8; ++nt)
#pragma unroll
            for (int r = 0; r < 4; ++r) acc[mt][nt][r] *= fsc;

    // ---- diagonal (only i == j CTAs) -------------------------------------
    if (i == j) {
        float diagv = 0.0f;
#pragma unroll
        for (int mt = 0; mt < 2; ++mt)
#pragma unroll
            for (int nt = 0; nt < 8; ++nt) {
                int lr = wr * 32 + mt * 16 + (lane >> 2);
                int c0 = wc * 64 + nt * 8 + ((lane & 3) << 1);
                if (c0     == lr    ) diagv += acc[mt][nt][0];
                if (c0 + 1 == lr    ) diagv += acc[mt][nt][1];
                if (c0     == lr + 8) diagv += acc[mt][nt][2];
                if (c0 + 1 == lr + 8) diagv += acc[mt][nt][3];
            }
        sred[tid] = diagv;
        __syncthreads();
        for (int off = 128; off >= 1; off >>= 1) {
            if (tid < off) sred[tid] += sred[tid + off];
            __syncthreads();
        }
        if (tid == 0) g_diagBlk[i] = sred[0];
    }

    // ---- row stats (per warp-half: 128 rows x 64 cols) -------------------
#pragma unroll
    for (int mt = 0; mt < 2; ++mt) {
        float m0 = -1e30f, m1 = -1e30f;
#pragma unroll
        for (int nt = 0; nt < 8; ++nt) {
            m0 = fmaxf(m0, fmaxf(acc[mt][nt][0], acc[mt][nt][1]));
            m1 = fmaxf(m1, fmaxf(acc[mt][nt][2], acc[mt][nt][3]));
        }
        const float lm0 = m0, lm1 = m1;
        m0 = fmaxf(m0, __shfl_xor_sync(0xffffffffu, m0, 1));
        m0 = fmaxf(m0, __shfl_xor_sync(0xffffffffu, m0, 2));
        m1 = fmaxf(m1, __shfl_xor_sync(0xffffffffu, m1, 1));
        m1 = fmaxf(m1, __shfl_xor_sync(0xffffffffu, m1, 2));
        float s0 = 0.0f, s1 = 0.0f;
        if (lm0 > m0 - SKIP_THR) {
#pragma unroll
            for (int nt = 0; nt < 8; ++nt) {
                float v0 = acc[mt][nt][0], v1 = acc[mt][nt][1];
                if (fmaxf(v0, v1) > m0 - SKIP_THR)
                    s0 += exp2f(v0 - m0) + exp2f(v1 - m0);
            }
        }
        if (lm1 > m1 - SKIP_THR) {
#pragma unroll
            for (int nt = 0; nt < 8; ++nt) {
                float v2 = acc[mt][nt][2], v3 = acc[mt][nt][3];
                if (fmaxf(v2, v3) > m1 - SKIP_THR)
                    s1 += exp2f(v2 - m1) + exp2f(v3 - m1);
            }
        }
        s0 += __shfl_xor_sync(0xffffffffu, s0, 1);
        s0 += __shfl_xor_sync(0xffffffffu, s0, 2);
        s1 += __shfl_xor_sync(0xffffffffu, s1, 1);
        s1 += __shfl_xor_sync(0xffffffffu, s1, 2);
        if ((lane & 3) == 0) {
            int r = i * 128 + wr * 32 + mt * 16 + (lane >> 2);
            size_t o = (size_t)(j * 2 + wc) * NTOK + r;
            g_rowM[o]     = m0;  g_rowS[o]     = s0;
            g_rowM[o + 8] = m1;  g_rowS[o + 8] = s1;
        }
    }

    // ---- col stats (per warp-quarter: 32 rows x 128 cols) ----------------
#pragma unroll
    for (int nt = 0; nt < 8; ++nt)
#pragma unroll
        for (int q = 0; q < 2; ++q) {
            float v0 = acc[0][nt][q],     v1 = acc[0][nt][q + 2];
            float v2 = acc[1][nt][q],     v3 = acc[1][nt][q + 2];
            float cm = fmaxf(fmaxf(v0, v1), fmaxf(v2, v3));
            const float lc = cm;
            cm = fmaxf(cm, __shfl_xor_sync(0xffffffffu, cm, 4));
            cm = fmaxf(cm, __shfl_xor_sync(0xffffffffu, cm, 8));
            cm = fmaxf(cm, __shfl_xor_sync(0xffffffffu, cm, 16));
            float cs = 0.0f;
            if (lc > cm - SKIP_THR) {
                if (fmaxf(v0, v1) > cm - SKIP_THR)
                    cs += exp2f(v0 - cm) + exp2f(v1 - cm);
                if (fmaxf(v2, v3) > cm - SKIP_THR)
                    cs += exp2f(v2 - cm) + exp2f(v3 - cm);
            }
            cs += __shfl_xor_sync(0xffffffffu, cs, 4);
            cs += __shfl_xor_sync(0xffffffffu, cs, 8);
            cs += __shfl_xor_sync(0xffffffffu, cs, 16);
            if (lane < 4) {
                int c = j * 128 + wc * 64 + nt * 8 + lane * 2 + q;
                size_t o = (size_t)(i * 4 + wr) * NTOK + c;
                g_colM[o] = cm;  g_colS[o] = cs;
            }
        }
}

// ---------------------------------------------------------------------------
// Kernel 2a: merge 256 row partials per row -> row LSE, sum per block.
// ---------------------------------------------------------------------------
__global__ void __launch_bounds__(128)
reduce_row_kernel()
{
    __shared__ float sr[128];
    const int row = blockIdx.x * 128 + threadIdx.x;
    float m = -1e30f, S = 0.0f;
    for (int p = 0; p < 256; ++p) {
        float mm = g_rowM[(size_t)p * NTOK + row];
        float ss = g_rowS[(size_t)p * NTOK + row];
        if (mm > m)            { S = S * exp2f(m - mm) + ss; m = mm; }
        else if (mm > m - 64.f)  S += ss * exp2f(mm - m);
    }
    sr[threadIdx.x] = m + log2f(S);
    __syncthreads();
    for (int off = 64; off >= 1; off >>= 1) {
        if (threadIdx.x < off) sr[threadIdx.x] += sr[threadIdx.x + off];
        __syncthreads();
    }
    if (threadIdx.x == 0) g_lseR[blockIdx.x] = sr[0];
}

// ---------------------------------------------------------------------------
// Kernel 2b: merge 512 col partials per col -> col LSE, sum per block.
// ---------------------------------------------------------------------------
__global__ void __launch_bounds__(128)
reduce_col_kernel()
{
    __shared__ float sr[128];
    const int col = blockIdx.x * 128 + threadIdx.x;
    float m = -1e30f, S = 0.0f;
    for (int p = 0; p < 512; ++p) {
        float mm = g_colM[(size_t)p * NTOK + col];
        float ss = g_colS[(size_t)p * NTOK + col];
        if (mm > m)            { S = S * exp2f(m - mm) + ss; m = mm; }
        else if (mm > m - 64.f)  S += ss * exp2f(mm - m);
    }
    sr[threadIdx.x] = m + log2f(S);
    __syncthreads();
    for (int off = 64; off >= 1; off >>= 1) {
        if (threadIdx.x < off) sr[threadIdx.x] += sr[threadIdx.x + off];
        __syncthreads();
    }
    if (threadIdx.x == 0) g_lseC[blockIdx.x] = sr[0];
}

// ---------------------------------------------------------------------------
// Kernel 3: final scalar combine.
// ---------------------------------------------------------------------------
__global__ void __launch_bounds__(128)
clip_final_kernel(float* __restrict__ out)
{
    __shared__ double sd[128];
    const int t = threadIdx.x;
    sd[t] = 0.5 * ((double)g_lseR[t] + (double)g_lseC[t]) - (double)g_diagBlk[t];
    __syncthreads();
    for (int off = 64; off >= 1; off >>= 1) {
        if (t < off) sd[t] += sd[t + off];
        __syncthreads();
    }
    if (t == 0) out[0] = (float)(LN2_D * sd[0] / (double)NTOK);
}

// ---------------------------------------------------------------------------
extern "C" void kernel_launch(void* const* d_in, const int* in_sizes, int n_in,
                              void* d_out, int out_size)
{
    const float* img   = (const float*)d_in[0];
    const float* txt   = (const float*)d_in[1];
    const float* scale = (const float*)d_in[2];
    float* out = (float*)d_out;

    convert_kernel<<<16384, 256>>>(img, txt);
    clip_mma_kernel<<<dim3(NT, NT), 256>>>(scale);
    reduce_row_kernel<<<128, 128>>>();
    reduce_col_kernel<<<128, 128>>>();
    clip_final_kernel<<<1, 128>>>(out);
}

// round 6
// speedup vs baseline: 8.1019x; 1.5254x over previous
#include <cuda_runtime.h>
#include <cuda_bf16.h>
#include <math.h>
#include <stdint.h>

// ===========================================================================
// CLIP contrastive loss, single-pass warp-MMA (mma.sync bf16, sm_100-safe) v2.
//   - CTA-internal merge of row/col softmax partials (128 partials each)
//   - float2-packed scratch (32 MB total vs 100 MB)
//   - BK=64 mainloop, dynamic smem, forced 2 CTAs/SM
// ===========================================================================

#define NTOK 16384
#define DK   512
#define NT   128            // 128x128 tiles per dimension
#define NSTG 8              // K stages of 64
#define STAGE_BYTES 18432   // 128 rows * 144 B (64 bf16 + 8 pad)

#define LOG2E_F 1.4426950408889634f
#define LN2_D   0.6931471805599453
#define SKIP_THR 25.0f

// ------------------------- device scratch ---------------------------------
__device__ __nv_bfloat16 g_bfA[NTOK * DK];      // image bf16 (16 MB)
__device__ __nv_bfloat16 g_bfB[NTOK * DK];      // text  bf16 (16 MB)
__device__ float2 g_row[128u * NTOK];           // [j][row] (m,s)  (16 MB)
__device__ float2 g_col[128u * NTOK];           // [i][col] (m,s)  (16 MB)
__device__ float g_diagBlk[NT];
__device__ float g_lseR[128];
__device__ float g_lseC[128];

// ------------------------- PTX helpers ------------------------------------
__device__ __forceinline__ uint32_t smem_u32(const void* p) {
    uint32_t a;
    asm("{ .reg .u64 t; cvta.to.shared.u64 t, %1; cvt.u32.u64 %0, t; }"
        : "=r"(a) : "l"(p));
    return a;
}
__device__ __forceinline__ void cpasync16(uint32_t dst, const void* src) {
    asm volatile("cp.async.cg.shared.global [%0], [%1], 16;"
                 :: "r"(dst), "l"(src) : "memory");
}
#define CP_COMMIT() asm volatile("cp.async.commit_group;" ::: "memory")

__device__ __forceinline__ void ldsm_x4(uint32_t* r, uint32_t addr) {
    asm volatile("ldmatrix.sync.aligned.m8n8.x4.shared.b16 {%0,%1,%2,%3}, [%4];"
                 : "=r"(r[0]), "=r"(r[1]), "=r"(r[2]), "=r"(r[3]) : "r"(addr));
}
__device__ __forceinline__ void mma16816(float* d, const uint32_t* a,
                                         const uint32_t* b) {
    asm volatile(
        "mma.sync.aligned.m16n8k16.row.col.f32.bf16.bf16.f32 "
        "{%0,%1,%2,%3}, {%4,%5,%6,%7}, {%8,%9}, {%0,%1,%2,%3};"
        : "+f"(d[0]), "+f"(d[1]), "+f"(d[2]), "+f"(d[3])
        : "r"(a[0]), "r"(a[1]), "r"(a[2]), "r"(a[3]), "r"(b[0]), "r"(b[1]));
}

__device__ __forceinline__ float2 merge2(float2 a, float2 b) {
    float M = fmaxf(a.x, b.x);
    float S = a.y * exp2f(a.x - M) + b.y * exp2f(b.x - M);
    return make_float2(M, S);
}

// ---------------------------------------------------------------------------
// Kernel 0: fp32 -> bf16 conversion of both inputs.
// ---------------------------------------------------------------------------
__global__ void __launch_bounds__(256)
convert_kernel(const float* __restrict__ A, const float* __restrict__ B)
{
    const int gb = blockIdx.x;
    const bool isB = (gb >= 8192);
    const float* src = isB ? B : A;
    __nv_bfloat16* dst = isB ? g_bfB : g_bfA;
    size_t i = ((size_t)(gb & 8191) * 256 + threadIdx.x) * 4;
    float4 v = *(const float4*)(src + i);
    *(__nv_bfloat162*)(dst + i)     = __floats2bfloat162_rn(v.x, v.y);
    *(__nv_bfloat162*)(dst + i + 2) = __floats2bfloat162_rn(v.z, v.w);
}

// ---------------------------------------------------------------------------
// stage loader: A and B 128x64 bf16 chunks into padded smem (144 B rows).
// ---------------------------------------------------------------------------
__device__ __forceinline__ void load_stage(uint32_t dA, uint32_t dB,
                                           const __nv_bfloat16* Ab,
                                           const __nv_bfloat16* Bb,
                                           int kb, int tid)
{
#pragma unroll
    for (int t = 0; t < 4; ++t) {
        int idx = tid + t * 256;         // 0..1023
        int row = idx >> 3;              // 0..127
        int ch  = idx & 7;               // 0..7, 16B each
        size_t gsrc = (size_t)row * 1024 + (size_t)kb * 128 + ch * 16;  // bytes
        uint32_t doff = row * 144 + ch * 16;                            // bytes
        cpasync16(dA + doff, (const char*)Ab + gsrc);
        cpasync16(dB + doff, (const char*)Bb + gsrc);
    }
}

// ---------------------------------------------------------------------------
// Kernel 1: fused GEMM + row/col softmax stats. grid=(128,128), 256 threads.
// ---------------------------------------------------------------------------
__global__ void __launch_bounds__(256, 2)
clip_mma_kernel(const float* __restrict__ scale_p)
{
    extern __shared__ __align__(16) char dynsmem[];
    __shared__ float sred[256];
    __shared__ float2 srow[2][128];
    __shared__ float2 scol[4][128];

    const int tid  = threadIdx.x;
    const int lane = tid & 31;
    const int warp = tid >> 5;
    const int wr   = warp & 3;           // row quarter: rows wr*32..+32
    const int wc   = warp >> 2;          // col half:    cols wc*64..+64
    const int j = blockIdx.x, i = blockIdx.y;

    const __nv_bfloat16* Ab = g_bfA + (size_t)i * 128 * DK;
    const __nv_bfloat16* Bb = g_bfB + (size_t)j * 128 * DK;
    const float fsc = scale_p[0] * LOG2E_F;

    float acc[2][8][4];
#pragma unroll
    for (int mt = 0; mt < 2; ++mt)
#pragma unroll
        for (int nt = 0; nt < 8; ++nt)
#pragma unroll
            for (int r = 0; r < 4; ++r) acc[mt][nt][r] = 0.0f;

    const uint32_t aS = smem_u32(dynsmem);
    const uint32_t bS = aS + 2 * STAGE_BYTES;
    // ldmatrix per-thread address components (bytes, within a stage)
    const uint32_t aOff = (wr * 32 + (lane & 15)) * 144 + ((lane >> 4) << 4);
    const uint32_t bOff = (wc * 64 + (lane & 7) + ((lane >> 4) << 3)) * 144
                          + (((lane >> 3) & 1) << 4);

    load_stage(aS, bS, Ab, Bb, 0, tid);
    CP_COMMIT();
    load_stage(aS + STAGE_BYTES, bS + STAGE_BYTES, Ab, Bb, 1, tid);
    CP_COMMIT();

    for (int kb = 0; kb < NSTG; ++kb) {
        const int s = kb & 1;
        if (kb < NSTG - 1) asm volatile("cp.async.wait_group 1;" ::: "memory");
        else               asm volatile("cp.async.wait_group 0;" ::: "memory");
        __syncthreads();

        const uint32_t aBase = aS + s * STAGE_BYTES + aOff;
        const uint32_t bBase = bS + s * STAGE_BYTES + bOff;
#pragma unroll
        for (int kk = 0; kk < 4; ++kk) {
            uint32_t a[2][4], b[4][4];
            ldsm_x4(a[0], aBase + kk * 32);
            ldsm_x4(a[1], aBase + kk * 32 + 16 * 144);
#pragma unroll
            for (int p = 0; p < 4; ++p)
                ldsm_x4(b[p], bBase + kk * 32 + p * 16 * 144);
#pragma unroll
            for (int mt = 0; mt < 2; ++mt)
#pragma unroll
                for (int p = 0; p < 4; ++p) {
                    mma16816(acc[mt][2 * p],     a[mt], &b[p][0]);
                    mma16816(acc[mt][2 * p + 1], a[mt], &b[p][2]);
                }
        }
        __syncthreads();
        if (kb <= NSTG - 3) {
            load_stage(aS + s * STAGE_BYTES, bS + s * STAGE_BYTES, Ab, Bb,
                       kb + 2, tid);
            CP_COMMIT();
        }
    }

    // ---- scale into log2 units -------------------------------------------
#pragma unroll
    for (int mt = 0; mt < 2; ++mt)
#pragma unroll
        for (int nt = 0; nt < 8; ++nt)
#pragma unroll
            for (int r = 0; r < 4; ++r) acc[mt][nt][r] *= fsc;

    // ---- diagonal (only i == j CTAs) -------------------------------------
    if (i == j) {
        float diagv = 0.0f;
#pragma unroll
        for (int mt = 0; mt < 2; ++mt)
#pragma unroll
            for (int nt = 0; nt < 8; ++nt) {
                int lr = wr * 32 + mt * 16 + (lane >> 2);
                int c0 = wc * 64 + nt * 8 + ((lane & 3) << 1);
                if (c0     == lr    ) diagv += acc[mt][nt][0];
                if (c0 + 1 == lr    ) diagv += acc[mt][nt][1];
                if (c0     == lr + 8) diagv += acc[mt][nt][2];
                if (c0 + 1 == lr + 8) diagv += acc[mt][nt][3];
            }
        sred[tid] = diagv;
        __syncthreads();
        for (int off = 128; off >= 1; off >>= 1) {
            if (tid < off) sred[tid] += sred[tid + off];
            __syncthreads();
        }
        if (tid == 0) g_diagBlk[i] = sred[0];
        __syncthreads();
    }

    // ---- row stats (per warp-half: 16-row groups x 64 cols) --------------
#pragma unroll
    for (int mt = 0; mt < 2; ++mt) {
        float m0 = -1e30f, m1 = -1e30f;
#pragma unroll
        for (int nt = 0; nt < 8; ++nt) {
            m0 = fmaxf(m0, fmaxf(acc[mt][nt][0], acc[mt][nt][1]));
            m1 = fmaxf(m1, fmaxf(acc[mt][nt][2], acc[mt][nt][3]));
        }
        const float lm0 = m0, lm1 = m1;
        m0 = fmaxf(m0, __shfl_xor_sync(0xffffffffu, m0, 1));
        m0 = fmaxf(m0, __shfl_xor_sync(0xffffffffu, m0, 2));
        m1 = fmaxf(m1, __shfl_xor_sync(0xffffffffu, m1, 1));
        m1 = fmaxf(m1, __shfl_xor_sync(0xffffffffu, m1, 2));
        float s0 = 0.0f, s1 = 0.0f;
        if (lm0 > m0 - SKIP_THR) {
#pragma unroll
            for (int nt = 0; nt < 8; ++nt) {
                float v0 = acc[mt][nt][0], v1 = acc[mt][nt][1];
                if (fmaxf(v0, v1) > m0 - SKIP_THR)
                    s0 += exp2f(v0 - m0) + exp2f(v1 - m0);
            }
        }
        if (lm1 > m1 - SKIP_THR) {
#pragma unroll
            for (int nt = 0; nt < 8; ++nt) {
                float v2 = acc[mt][nt][2], v3 = acc[mt][nt][3];
                if (fmaxf(v2, v3) > m1 - SKIP_THR)
                    s1 += exp2f(v2 - m1) + exp2f(v3 - m1);
            }
        }
        s0 += __shfl_xor_sync(0xffffffffu, s0, 1);
        s0 += __shfl_xor_sync(0xffffffffu, s0, 2);
        s1 += __shfl_xor_sync(0xffffffffu, s1, 1);
        s1 += __shfl_xor_sync(0xffffffffu, s1, 2);
        if ((lane & 3) == 0) {
            int rl = wr * 32 + mt * 16 + (lane >> 2);
            srow[wc][rl]     = make_float2(m0, s0);
            srow[wc][rl + 8] = make_float2(m1, s1);
        }
    }

    // ---- col stats (per warp-quarter: 32 rows x its 8-col groups) --------
#pragma unroll
    for (int nt = 0; nt < 8; ++nt)
#pragma unroll
        for (int q = 0; q < 2; ++q) {
            float v0 = acc[0][nt][q],     v1 = acc[0][nt][q + 2];
            float v2 = acc[1][nt][q],     v3 = acc[1][nt][q + 2];
            float cm = fmaxf(fmaxf(v0, v1), fmaxf(v2, v3));
            const float lc = cm;
            cm = fmaxf(cm, __shfl_xor_sync(0xffffffffu, cm, 4));
            cm = fmaxf(cm, __shfl_xor_sync(0xffffffffu, cm, 8));
            cm = fmaxf(cm, __shfl_xor_sync(0xffffffffu, cm, 16));
            float cs = 0.0f;
            if (lc > cm - SKIP_THR) {
                if (fmaxf(v0, v1) > cm - SKIP_THR)
                    cs += exp2f(v0 - cm) + exp2f(v1 - cm);
                if (fmaxf(v2, v3) > cm - SKIP_THR)
                    cs += exp2f(v2 - cm) + exp2f(v3 - cm);
            }
            cs += __shfl_xor_sync(0xffffffffu, cs, 4);
            cs += __shfl_xor_sync(0xffffffffu, cs, 8);
            cs += __shfl_xor_sync(0xffffffffu, cs, 16);
            if (lane < 4) {
                int cl = wc * 64 + nt * 8 + lane * 2 + q;
                scol[wr][cl] = make_float2(cm, cs);
            }
        }

    // ---- CTA-internal merge + single store per row/col -------------------
    __syncthreads();
    if (tid < 128) {
        float2 r = merge2(srow[0][tid], srow[1][tid]);
        g_row[(size_t)j * NTOK + i * 128 + tid] = r;
        float2 c = merge2(merge2(scol[0][tid], scol[1][tid]),
                          merge2(scol[2][tid], scol[3][tid]));
        g_col[(size_t)i * NTOK + j * 128 + tid] = c;
    }
}

// ---------------------------------------------------------------------------
// Kernel 2a/2b: merge 128 partials per row/col -> LSE, sum per block.
// grid=128, block=256 (two threads per row/col, 64 partials each).
// ---------------------------------------------------------------------------
__global__ void __launch_bounds__(256)
reduce_row_kernel()
{
    __shared__ float2 sp[256];
    __shared__ float sl[128];
    const int tid = threadIdx.x;
    const int half = tid >> 7, rl = tid & 127;
    const int row = blockIdx.x * 128 + rl;

    float m = -1e30f, S = 0.0f;
#pragma unroll 4
    for (int p = half * 64; p < half * 64 + 64; ++p) {
        float2 v = g_row[(size_t)p * NTOK + row];
        if (v.x > m) { S = S * exp2f(m - v.x) + v.y; m = v.x; }
        else         { S += v.y * exp2f(v.x - m); }
    }
    sp[tid] = make_float2(m, S);
    __syncthreads();
    if (tid < 128) {
        float2 t = merge2(sp[tid], sp[tid + 128]);
        sl[tid] = t.x + log2f(t.y);
    }
    __syncthreads();
    for (int off = 64; off >= 1; off >>= 1) {
        if (tid < off) sl[tid] += sl[tid + off];
        __syncthreads();
    }
    if (tid == 0) g_lseR[blockIdx.x] = sl[0];
}

__global__ void __launch_bounds__(256)
reduce_col_kernel()
{
    __shared__ float2 sp[256];
    __shared__ float sl[128];
    const int tid = threadIdx.x;
    const int half = tid >> 7, cl = tid & 127;
    const int col = blockIdx.x * 128 + cl;

    float m = -1e30f, S = 0.0f;
#pragma unroll 4
    for (int p = half * 64; p < half * 64 + 64; ++p) {
        float2 v = g_col[(size_t)p * NTOK + col];
        if (v.x > m) { S = S * exp2f(m - v.x) + v.y; m = v.x; }
        else         { S += v.y * exp2f(v.x - m); }
    }
    sp[tid] = make_float2(m, S);
    __syncthreads();
    if (tid < 128) {
        float2 t = merge2(sp[tid], sp[tid + 128]);
        sl[tid] = t.x + log2f(t.y);
    }
    __syncthreads();
    for (int off = 64; off >= 1; off >>= 1) {
        if (tid < off) sl[tid] += sl[tid + off];
        __syncthreads();
    }
    if (tid == 0) g_lseC[blockIdx.x] = sl[0];
}

// ---------------------------------------------------------------------------
// Kernel 3: final scalar combine.
// ---------------------------------------------------------------------------
__global__ void __launch_bounds__(128)
clip_final_kernel(float* __restrict__ out)
{
    __shared__ double sd[128];
    const int t = threadIdx.x;
    sd[t] = 0.5 * ((double)g_lseR[t] + (double)g_lseC[t]) - (double)g_diagBlk[t];
    __syncthreads();
    for (int off = 64; off >= 1; off >>= 1) {
        if (t < off) sd[t] += sd[t + off];
        __syncthreads();
    }
    if (t == 0) out[0] = (float)(LN2_D * sd[0] / (double)NTOK);
}

// ---------------------------------------------------------------------------
extern "C" void kernel_launch(void* const* d_in, const int* in_sizes, int n_in,
                              void* d_out, int out_size)
{
    const float* img   = (const float*)d_in[0];
    const float* txt   = (const float*)d_in[1];
    const float* scale = (const float*)d_in[2];
    float* out = (float*)d_out;

    cudaFuncSetAttribute(clip_mma_kernel,
                         cudaFuncAttributeMaxDynamicSharedMemorySize,
                         4 * STAGE_BYTES);

    convert_kernel<<<16384, 256>>>(img, txt);
    clip_mma_kernel<<<dim3(NT, NT), 256, 4 * STAGE_BYTES>>>(scale);
    reduce_row_kernel<<<128, 256>>>();
    reduce_col_kernel<<<128, 256>>>();
    clip_final_kernel<<<1, 128>>>(out);
}